// round 15
// baseline (speedup 1.0000x reference)
#include <cuda_runtime.h>
#include <cuda_bf16.h>
#include <cstdint>

#define BB   16
#define C_IN 256
#define CRr  128
#define KKGc 144
#define HWn  3136
#define HH   56
#define WWc  56
#define NCTA 448   // 28 n-tiles x 16 batches (gemm1 grid, stats partials)

typedef unsigned long long ull;

// ---------------- scratch (allocation-free: __device__ globals) ----------------
__device__ float g_t[(size_t)BB * CRr * HWn];     // reduce-conv output  [b][cr][hw]
__device__ float g_kern[(size_t)BB * KKGc * HWn]; // span-conv output    [b][o][hw]
__device__ float g_scale[CRr];
__device__ float g_shift[CRr];
__device__ float g_bns[CRr][NCTA];                // per-CTA partial sums (raw acc)
__device__ float g_bnq[CRr][NCTA];                // per-CTA partial sumsq

// A-fragment arrays (mma layout), [kstep][mtile][lane] -> uint4 (a0..a3)
__device__ uint4 g_af1h[16 * 8 * 32], g_af1l[16 * 8 * 32];   // w_reduce 128x256
__device__ uint4 g_af2h[8 * 9 * 32],  g_af2l[8 * 9 * 32];    // w_span  144x128

// ---------------- helpers ----------------
__device__ __forceinline__ uint32_t packbf(float e0, float e1) {
    uint32_t r;
    asm("cvt.rn.bf16x2.f32 %0, %1, %2;" : "=r"(r) : "f"(e1), "f"(e0));
    return r;
}
__device__ __forceinline__ float bf_lo(uint32_t h) { return __uint_as_float(h << 16); }
__device__ __forceinline__ float bf_hi(uint32_t h) { return __uint_as_float(h & 0xFFFF0000u); }

__device__ __forceinline__ void mma_bf16(float* c, const uint4& a,
                                         uint32_t b0, uint32_t b1) {
    asm volatile(
        "mma.sync.aligned.m16n8k16.row.col.f32.bf16.bf16.f32 "
        "{%0,%1,%2,%3}, {%4,%5,%6,%7}, {%8,%9}, {%0,%1,%2,%3};"
        : "+f"(c[0]), "+f"(c[1]), "+f"(c[2]), "+f"(c[3])
        : "r"(a.x), "r"(a.y), "r"(a.z), "r"(a.w), "r"(b0), "r"(b1));
}
__device__ __forceinline__ uint32_t smem_u32(const void* p) {
    uint32_t a;
    asm("{ .reg .u64 t; cvta.to.shared.u64 t, %1; cvt.u32.u64 %0, t; }"
        : "=r"(a) : "l"(p));
    return a;
}
__device__ __forceinline__ void cp16(uint32_t dst, const void* src) {
    asm volatile("cp.async.cg.shared.global [%0], [%1], 16;"
                 :: "r"(dst), "l"(src) : "memory");
}
#define CP_COMMIT() asm volatile("cp.async.commit_group;" ::: "memory")
#define CP_WAIT0()  asm volatile("cp.async.wait_group 0;"  ::: "memory")

// packed fp32x2
__device__ __forceinline__ void fma2(ull& acc, ull a, ull b) {
    asm("fma.rn.f32x2 %0, %1, %2, %0;" : "+l"(acc) : "l"(a), "l"(b));
}
__device__ __forceinline__ ull pack2(float lo, float hi) {
    ull r; asm("mov.b64 %0, {%1, %2};" : "=l"(r) : "f"(lo), "f"(hi)); return r;
}
__device__ __forceinline__ void unpack2(ull v, float& lo, float& hi) {
    asm("mov.b64 {%0, %1}, %2;" : "=f"(lo), "=f"(hi) : "l"(v));
}

// ---------------------------------------------------------------------------
// Prep (merged): convert both weight matrices into mma A-fragments.
// ---------------------------------------------------------------------------
__device__ __forceinline__ void prep_one(const float* __restrict__ W,
                                         uint4* __restrict__ hi,
                                         uint4* __restrict__ lo,
                                         int blk, int MT, int ldk, int lane)
{
    const int mt  = blk % MT;
    const int ks  = blk / MT;
    const int g   = lane >> 2;
    const int tc2 = (lane & 3) * 2;
    const float* w0 = W + (size_t)(mt * 16 + g)     * ldk + ks * 16 + tc2;
    const float* w1 = W + (size_t)(mt * 16 + g + 8) * ldk + ks * 16 + tc2;

    const float a00 = w0[0], a01 = w0[1], a08 = w0[8], a09 = w0[9];
    const float b00 = w1[0], b01 = w1[1], b08 = w1[8], b09 = w1[9];

    uint4 H, L;
    H.x = packbf(a00, a01); H.y = packbf(b00, b01);
    H.z = packbf(a08, a09); H.w = packbf(b08, b09);
    L.x = packbf(a00 - bf_lo(H.x), a01 - bf_hi(H.x));
    L.y = packbf(b00 - bf_lo(H.y), b01 - bf_hi(H.y));
    L.z = packbf(a08 - bf_lo(H.z), a09 - bf_hi(H.z));
    L.w = packbf(b08 - bf_lo(H.w), b09 - bf_hi(H.w));

    hi[blk * 32 + lane] = H;
    lo[blk * 32 + lane] = L;
}

__global__ void prep_all(const float* __restrict__ w_reduce,
                         const float* __restrict__ w_span)
{
    const int lane = threadIdx.x;
    const int blk  = blockIdx.x;
    if (blk < 128) prep_one(w_reduce, g_af1h, g_af1l, blk, 8, C_IN, lane);
    else           prep_one(w_span,   g_af2h, g_af2l, blk - 128, 9, CRr, lane);
}

// ---------------------------------------------------------------------------
// Tensor-core GEMM via mma.sync bf16, 3-pass split (hh + hl + lh), fp32 acc.
// Pipelined staging; pass-outer MMA ordering for ILP (same-acc writes are
// 2*MT independent MMAs apart instead of back-to-back).
// ---------------------------------------------------------------------------
template<int MT, int K, bool SPAN, bool STATS>
__global__ __launch_bounds__(224, 2)
void gemm_mma(const uint4* __restrict__ afh, const uint4* __restrict__ afl,
              const float* __restrict__ bias, const float* __restrict__ X)
{
    constexpr int KT      = K / 32;
    constexpr int A_ELEMS = 2 * MT * 32;
    constexpr int A_BYTES = A_ELEMS * 16;
    extern __shared__ __align__(16) char smem[];
    const uint32_t sbase = smem_u32(smem);
    uint16_t (*sBh)[34] = reinterpret_cast<uint16_t(*)[34]>(smem + 4 * A_BYTES);
    uint16_t (*sBl)[34] = reinterpret_cast<uint16_t(*)[34]>(smem + 4 * A_BYTES + 7616);
    float* s_sc = reinterpret_cast<float*>(smem + 4 * A_BYTES + 15232);           // [K]
    float* s_sh = reinterpret_cast<float*>(smem + 4 * A_BYTES + 15232 + 512);     // [K]
    float (*sS)[8] = reinterpret_cast<float(*)[8]>(smem + 4 * A_BYTES + 16256);
    float (*sQ)[8] = reinterpret_cast<float(*)[8]>(smem + 4 * A_BYTES + 16256 + 4096);

    const int tid  = threadIdx.x;
    const int wid  = tid >> 5;
    const int lane = tid & 31;
    const int n0   = blockIdx.x * 112;
    const int b    = blockIdx.z;

    const float* Bin = SPAN ? (g_t + (size_t)b * K * HWn)
                            : (X   + (size_t)b * K * HWn);
    float* Cout = SPAN ? (g_kern + (size_t)b * KKGc * HWn)
                       : (g_t    + (size_t)b * CRr  * HWn);

    float acc[MT][8] = {};

    const int g   = lane >> 2;
    const int tc2 = (lane & 3) * 2;
    const int nw  = wid * 16;

    const int bk0 = tid / 112;
    const int bnn = tid - bk0 * 112;

    float bregs[16];

    if constexpr (SPAN) {
        if (tid < K) { s_sc[tid] = g_scale[tid]; s_sh[tid] = g_shift[tid]; }
        __syncthreads();
    }

    auto loadBregs = [&](int kt) {
        const float* bp = Bin + (size_t)(kt * 32 + bk0) * HWn + n0 + bnn;
        #pragma unroll
        for (int p = 0; p < 16; p++)
            bregs[p] = bp[(size_t)(2 * p) * HWn];
    };
    auto storeB = [&](int kt) {
        const int kb = kt * 32;
        #pragma unroll
        for (int p = 0; p < 16; p++) {
            const int k = bk0 + 2 * p;
            float v = bregs[p];
            if constexpr (SPAN)
                v = fmaxf(fmaf(v, s_sc[kb + k], s_sh[kb + k]), 0.f);
            const __nv_bfloat16 h = __float2bfloat16(v);
            const __nv_bfloat16 l = __float2bfloat16(v - __bfloat162float(h));
            sBh[bnn][k] = __bfloat16_as_ushort(h);
            sBl[bnn][k] = __bfloat16_as_ushort(l);
        }
    };
    auto cpA = [&](int buf, int kt) {
        const uint4* sh = afh + (size_t)kt * A_ELEMS;
        const uint4* sl = afl + (size_t)kt * A_ELEMS;
        const uint32_t dh = sbase + buf * 2 * A_BYTES;
        const uint32_t dl = dh + A_BYTES;
        for (int i = tid; i < A_ELEMS; i += 224) {
            cp16(dh + i * 16, sh + i);
            cp16(dl + i * 16, sl + i);
        }
        CP_COMMIT();
    };

    cpA(0, 0);
    loadBregs(0);

    int buf = 0;
    for (int kt = 0; kt < KT; kt++) {
        const bool more = (kt + 1) < KT;

        storeB(kt);
        CP_WAIT0();
        __syncthreads();

        if (more) {
            cpA(buf ^ 1, kt + 1);
            loadBregs(kt + 1);
        }

        const uint4* sAh = reinterpret_cast<const uint4*>(smem + buf * 2 * A_BYTES);
        const uint4* sAl = reinterpret_cast<const uint4*>(smem + buf * 2 * A_BYTES + A_BYTES);
        #pragma unroll
        for (int s = 0; s < 2; s++) {
            uint32_t bh0[2], bh1[2], bl0[2], bl1[2];
            #pragma unroll
            for (int t = 0; t < 2; t++) {
                const int n  = nw + t * 8 + g;
                const int kk = s * 16 + tc2;
                bh0[t] = *reinterpret_cast<const uint32_t*>(&sBh[n][kk]);
                bh1[t] = *reinterpret_cast<const uint32_t*>(&sBh[n][kk + 8]);
                bl0[t] = *reinterpret_cast<const uint32_t*>(&sBl[n][kk]);
                bl1[t] = *reinterpret_cast<const uint32_t*>(&sBl[n][kk + 8]);
            }
            // pass-outer ordering: same-acc MMAs are 2*MT apart
            #pragma unroll
            for (int p = 0; p < 3; p++) {
                const uint4* src = (p == 2) ? sAl : sAh;
                #pragma unroll
                for (int m = 0; m < MT; m++) {
                    const uint4 a = src[(s * MT + m) * 32 + lane];
                    if (p == 1) {
                        mma_bf16(&acc[m][0], a, bl0[0], bl1[0]);
                        mma_bf16(&acc[m][4], a, bl0[1], bl1[1]);
                    } else {
                        mma_bf16(&acc[m][0], a, bh0[0], bh1[0]);
                        mma_bf16(&acc[m][4], a, bh0[1], bh1[1]);
                    }
                }
            }
        }

        if (more) __syncthreads();
        buf ^= 1;
    }

    #pragma unroll
    for (int m = 0; m < MT; m++) {
        const int r1 = m * 16 + g, r2 = r1 + 8;
        const float bv1 = bias[r1], bv2 = bias[r2];
        #pragma unroll
        for (int t = 0; t < 2; t++) {
            const int col = n0 + nw + t * 8 + tc2;
            float2 o1 = make_float2(acc[m][t * 4 + 0] + bv1,
                                    acc[m][t * 4 + 1] + bv1);
            float2 o2 = make_float2(acc[m][t * 4 + 2] + bv2,
                                    acc[m][t * 4 + 3] + bv2);
            *reinterpret_cast<float2*>(Cout + (size_t)r1 * HWn + col) = o1;
            *reinterpret_cast<float2*>(Cout + (size_t)r2 * HWn + col) = o2;
        }
    }

    if constexpr (STATS) {
        __syncthreads();
        #pragma unroll
        for (int m = 0; m < MT; m++) {
            float s1 = acc[m][0] + acc[m][1] + acc[m][4] + acc[m][5];
            float s2 = acc[m][2] + acc[m][3] + acc[m][6] + acc[m][7];
            float q1 = acc[m][0]*acc[m][0] + acc[m][1]*acc[m][1]
                     + acc[m][4]*acc[m][4] + acc[m][5]*acc[m][5];
            float q2 = acc[m][2]*acc[m][2] + acc[m][3]*acc[m][3]
                     + acc[m][6]*acc[m][6] + acc[m][7]*acc[m][7];
            s1 += __shfl_xor_sync(~0u, s1, 1); s1 += __shfl_xor_sync(~0u, s1, 2);
            s2 += __shfl_xor_sync(~0u, s2, 1); s2 += __shfl_xor_sync(~0u, s2, 2);
            q1 += __shfl_xor_sync(~0u, q1, 1); q1 += __shfl_xor_sync(~0u, q1, 2);
            q2 += __shfl_xor_sync(~0u, q2, 1); q2 += __shfl_xor_sync(~0u, q2, 2);
            if ((lane & 3) == 0) {
                sS[m * 16 + g][wid]     = s1;
                sS[m * 16 + g + 8][wid] = s2;
                sQ[m * 16 + g][wid]     = q1;
                sQ[m * 16 + g + 8][wid] = q2;
            }
        }
        __syncthreads();
        if (tid < 128) {
            float s = 0.f, q = 0.f;
            #pragma unroll
            for (int wdx = 0; wdx < 7; wdx++) { s += sS[tid][wdx]; q += sQ[tid][wdx]; }
            const int cta = blockIdx.z * 28 + blockIdx.x;
            g_bns[tid][cta] = s;
            g_bnq[tid][cta] = q;
        }
    }
}

#define A_B1 (2 * 8 * 32 * 16)
#define A_B2 (2 * 9 * 32 * 16)
#define SMEM1 (4 * A_B1 + 16256 + 8192)
#define SMEM2 (4 * A_B2 + 16256)

// ---------------------------------------------------------------------------
// BN finalize, parallel tree over 448 deterministic partials.
// ---------------------------------------------------------------------------
__global__ __launch_bounds__(256)
void bn_finalize(const float* __restrict__ gamma, const float* __restrict__ beta,
                 const float* __restrict__ b_reduce)
{
    const int c   = blockIdx.x;
    const int tid = threadIdx.x;
    __shared__ float ss[256], qq[256];

    float s = 0.f, q = 0.f;
    if (tid < NCTA)       { s += g_bns[c][tid];       q += g_bnq[c][tid]; }
    if (tid + 256 < NCTA) { s += g_bns[c][tid + 256]; q += g_bnq[c][tid + 256]; }
    ss[tid] = s; qq[tid] = q;
    __syncthreads();
    #pragma unroll
    for (int o = 128; o > 0; o >>= 1) {
        if (tid < o) { ss[tid] += ss[tid + o]; qq[tid] += qq[tid + o]; }
        __syncthreads();
    }
    if (tid == 0) {
        const float S    = ss[0], Q = qq[0];
        const float br   = b_reduce[c];
        const float N    = (float)(BB * HWn);
        const float mean = S / N + br;
        const float ex2  = (Q + 2.f * br * S) / N + br * br;
        const float var  = ex2 - mean * mean;
        const float rstd = rsqrtf(var + 1e-5f);
        const float sc   = gamma[c] * rstd;
        g_scale[c] = sc;
        g_shift[c] = beta[c] - mean * sc;
    }
}

// ---------------------------------------------------------------------------
// Involution gather, w-pair packed (f32x2).
// ---------------------------------------------------------------------------
#define THT 8
__global__ __launch_bounds__(224)
void involution_kernel(const float* __restrict__ x, float* __restrict__ out)
{
    __shared__ __align__(16) float sx[16][THT + 2][58];

    const int h0  = blockIdx.x * THT;
    const int g   = blockIdx.y;
    const int b   = blockIdx.z;
    const int tid = threadIdx.x;            // 0..223

    const int wp = tid % 28;                // w-pair index
    const int q  = tid / 28;                // 0..7 output row
    const int w  = wp * 2;

    const float* xg = x + ((size_t)b * C_IN + g * 16) * HWn;
    for (int p = tid; p < (THT + 2) * 58; p += 224) {
        const int r    = p / 58;
        const int cpos = p - r * 58;
        const int hh   = h0 - 1 + r;
        const int ww   = cpos - 1;
        const bool ok  = (hh >= 0) && (hh < HH) && (ww >= 0) && (ww < WWc);
        const float* src = xg + hh * WWc + ww;
        #pragma unroll
        for (int d = 0; d < 16; d++)
            sx[d][r][cpos] = ok ? src[(size_t)d * HWn] : 0.f;
    }

    const float* kg = g_kern + ((size_t)b * KKGc + g) * HWn + (h0 + q) * WWc + w;
    ull kt[9];
    #pragma unroll
    for (int t = 0; t < 9; t++)
        kt[t] = *reinterpret_cast<const ull*>(kg + (size_t)t * 16 * HWn);

    __syncthreads();

    float* og = out + ((size_t)b * C_IN + g * 16) * HWn + (h0 + q) * WWc + w;
    #pragma unroll
    for (int d = 0; d < 16; d++) {
        ull acc = 0;
        #pragma unroll
        for (int i = 0; i < 3; i++) {
            const float* row = &sx[d][q + i][w];
            const ull v01 = *reinterpret_cast<const ull*>(row);
            const ull v23 = *reinterpret_cast<const ull*>(row + 2);
            float v0, v1, v2, v3;
            unpack2(v01, v0, v1);
            unpack2(v23, v2, v3);
            const ull v12 = pack2(v1, v2);
            fma2(acc, v01, kt[i * 3 + 0]);
            fma2(acc, v12, kt[i * 3 + 1]);
            fma2(acc, v23, kt[i * 3 + 2]);
        }
        *reinterpret_cast<ull*>(og + (size_t)d * HWn) = acc;
    }
}

// ---------------------------------------------------------------------------
extern "C" void kernel_launch(void* const* d_in, const int* in_sizes, int n_in,
                              void* d_out, int out_size)
{
    (void)in_sizes; (void)n_in; (void)out_size;
    const float* x        = (const float*)d_in[0];
    const float* w_reduce = (const float*)d_in[1];
    const float* b_reduce = (const float*)d_in[2];
    const float* gamma    = (const float*)d_in[3];
    const float* beta     = (const float*)d_in[4];
    const float* w_span   = (const float*)d_in[5];
    const float* b_span   = (const float*)d_in[6];
    float* out = (float*)d_out;

    uint4 *af1h, *af1l, *af2h, *af2l;
    cudaGetSymbolAddress((void**)&af1h, g_af1h);
    cudaGetSymbolAddress((void**)&af1l, g_af1l);
    cudaGetSymbolAddress((void**)&af2h, g_af2h);
    cudaGetSymbolAddress((void**)&af2l, g_af2l);

    cudaFuncSetAttribute(gemm_mma<8, C_IN, false, true>,
                         cudaFuncAttributeMaxDynamicSharedMemorySize, SMEM1);
    cudaFuncSetAttribute(gemm_mma<9, CRr, true, false>,
                         cudaFuncAttributeMaxDynamicSharedMemorySize, SMEM2);

    // 0) weight fragment prep (merged, one launch)
    prep_all<<<128 + 72, 32>>>(w_reduce, w_span);

    // 1) reduce conv + fused BN partial stats (pipelined staging)
    gemm_mma<8, C_IN, false, true>
        <<<dim3(HWn / 112, 1, BB), 224, SMEM1>>>(af1h, af1l, b_reduce, x);

    // 2) BN finalize (parallel tree over 448 deterministic partials)
    bn_finalize<<<CRr, 256>>>(gamma, beta, b_reduce);

    // 3) span conv, all 144 rows (9 m-tiles), BN+ReLU fused at staging
    gemm_mma<9, CRr, true, false>
        <<<dim3(HWn / 112, 1, BB), 224, SMEM2>>>(af2h, af2l, b_span, nullptr);

    // 4) involution gather (w-pair packed)
    dim3 g3(HH / THT, 16, BB);
    involution_kernel<<<g3, 224>>>(x, out);
}